// round 2
// baseline (speedup 1.0000x reference)
#include <cuda_runtime.h>
#include <math.h>

// ---------------------------------------------------------------------------
// SinkhornLoss: m=8, n=2048, d=3.
// M[i,k] = max(||x_i||^2 + ||y_k||^2 - 2 x_i.y_k, 0)
// 50 log-domain Sinkhorn iterations with eps=1e-3, early-stop flag semantics
// replicated via per-iteration error slots. loss[b] = sum_{i,k} M * P.
// M is never materialized: recomputed from d=3 coords (FMA-bound, L1-resident).
// ---------------------------------------------------------------------------

#define MB     8
#define NB     2048
#define EPSF   1e-3f
#define THRESH 1e-3f
#define NITERS 50
// log2(e)/eps : exp(t/eps) == ex2(t * INVEPS_LOG2E)
#define INVEPS_LOG2E 1442.6950408889634f

#define WARPS_PER_BLOCK 4
#define ROWS_PER_WARP   8
#define ROWS_PER_BLOCK  (WARPS_PER_BLOCK * ROWS_PER_WARP)   // 32
#define BLOCKS_PER_BATCH (NB / ROWS_PER_BLOCK)               // 64
#define GRID_HALF (MB * BLOCKS_PER_BATCH)                    // 512

// Scratch (allocation-free rule: __device__ globals)
__device__ float4   g_xp[MB * NB];   // {x0,x1,x2, ||x||^2} predicted
__device__ float4   g_yp[MB * NB];   // {y0,y1,y2, ||y||^2} expected
__device__ float    g_u[MB * NB];
__device__ float    g_v[MB * NB];
__device__ float    g_la[MB * NB];   // log(a)
__device__ float    g_lb[MB * NB];   // log(b)
__device__ unsigned g_err[NITERS];   // per-iteration max(err_u, err_v), float bits

__device__ __forceinline__ float ex2f(float x) {
    float r;
    asm("ex2.approx.ftz.f32 %0, %1;" : "=f"(r) : "f"(x));
    return r;
}

// ---------------------------------------------------------------------------
__global__ void k_init(const float* __restrict__ px, const float* __restrict__ py,
                       const float* __restrict__ a, const float* __restrict__ b,
                       float* __restrict__ out) {
    int i = blockIdx.x * blockDim.x + threadIdx.x;
    if (i < MB * NB) {
        float x0 = px[3 * i], x1 = px[3 * i + 1], x2 = px[3 * i + 2];
        g_xp[i] = make_float4(x0, x1, x2, x0 * x0 + x1 * x1 + x2 * x2);
        float y0 = py[3 * i], y1 = py[3 * i + 1], y2 = py[3 * i + 2];
        g_yp[i] = make_float4(y0, y1, y2, y0 * y0 + y1 * y1 + y2 * y2);
        g_u[i] = 0.0f;
        g_v[i] = 0.0f;
        g_la[i] = logf(a[i]);
        g_lb[i] = logf(b[i]);
    }
    if (i < NITERS) g_err[i] = 0u;          // 0.0f bits
    if (i < MB)     out[i] = 0.0f;
}

// ---------------------------------------------------------------------------
// One half Sinkhorn update.
// SIDE=0: u_new[i] = eps*log_a[i] - eps*lse_k((v[k]-M[i,k])/eps)   (rows = x)
// SIDE=1: v_new[k] = eps*log_b[k] - eps*lse_i((u[i]-M[i,k])/eps)   (rows = y)
template <int SIDE>
__global__ void __launch_bounds__(128) k_half(int iter) {
    __shared__ int s_done;
    if (threadIdx.x == 0) {
        int d = 0;
        for (int s = 0; s < iter; s++)
            d |= (__uint_as_float(g_err[s]) < THRESH) ? 1 : 0;
        s_done = d;
    }
    __syncthreads();
    if (s_done) return;   // frozen: reference keeps u,v unchanged once converged

    const int warp = threadIdx.x >> 5;
    const int lane = threadIdx.x & 31;
    const int batch = blockIdx.x / BLOCKS_PER_BATCH;
    const int row0 = (blockIdx.x % BLOCKS_PER_BATCH) * ROWS_PER_BLOCK + warp * ROWS_PER_WARP;
    const int base = batch * NB;

    const float4* __restrict__ rp  = SIDE ? g_yp : g_xp;   // row-side coords
    const float4* __restrict__ cpk = SIDE ? g_xp : g_yp;   // col-side coords
    const float*  __restrict__ pot = SIDE ? g_u  : g_v;    // col-side potential
    float*                     upd = SIDE ? g_v  : g_u;    // potential being updated
    const float*  __restrict__ rl  = SIDE ? g_lb : g_la;   // row-side log marginal

    float4 R[ROWS_PER_WARP];
    float  mx[ROWS_PER_WARP];
#pragma unroll
    for (int j = 0; j < ROWS_PER_WARP; j++) {
        R[j] = rp[base + row0 + j];
        mx[j] = -3.4e38f;
    }

    // Pass 1: row-wise max of s = pot[k] - M
    for (int t = 0; t < NB / 32; t++) {
        int k = base + t * 32 + lane;
        float4 C = cpk[k];
        float  p = pot[k];
#pragma unroll
        for (int j = 0; j < ROWS_PER_WARP; j++) {
            float dot = R[j].x * C.x + R[j].y * C.y + R[j].z * C.z;
            float Mv  = fmaxf((R[j].w + C.w) - 2.0f * dot, 0.0f);
            mx[j] = fmaxf(mx[j], p - Mv);
        }
    }
#pragma unroll
    for (int j = 0; j < ROWS_PER_WARP; j++) {
#pragma unroll
        for (int o = 16; o; o >>= 1)
            mx[j] = fmaxf(mx[j], __shfl_xor_sync(0xffffffffu, mx[j], o));
    }

    // Pass 2: row-wise sum of exp((s - mx)/eps)
    float sm[ROWS_PER_WARP];
#pragma unroll
    for (int j = 0; j < ROWS_PER_WARP; j++) sm[j] = 0.0f;

    for (int t = 0; t < NB / 32; t++) {
        int k = base + t * 32 + lane;
        float4 C = cpk[k];
        float  p = pot[k];
#pragma unroll
        for (int j = 0; j < ROWS_PER_WARP; j++) {
            float dot = R[j].x * C.x + R[j].y * C.y + R[j].z * C.z;
            float Mv  = fmaxf((R[j].w + C.w) - 2.0f * dot, 0.0f);
            float tt  = (p - Mv) - mx[j];          // <= 0, exact 0 at the max
            sm[j] += ex2f(tt * INVEPS_LOG2E);
        }
    }
#pragma unroll
    for (int j = 0; j < ROWS_PER_WARP; j++) {
#pragma unroll
        for (int o = 16; o; o >>= 1)
            sm[j] += __shfl_xor_sync(0xffffffffu, sm[j], o);
    }

    // lse = mx/eps + ln(sm)  =>  new = eps*log_marg - mx - eps*ln(sm)
    if (lane == 0) {
        float e = 0.0f;
#pragma unroll
        for (int j = 0; j < ROWS_PER_WARP; j++) {
            int r = base + row0 + j;
            float nv = EPSF * rl[r] - mx[j] - EPSF * __logf(sm[j]);
            float ov = upd[r];
            upd[r] = nv;
            e = fmaxf(e, fabsf(nv - ov));
        }
        atomicMax(&g_err[iter], __float_as_uint(e));   // e >= 0: uint order == float order
    }
}

// ---------------------------------------------------------------------------
// loss[b] = sum_{i,k} M * exp((-M + u_i + v_k)/eps)
__global__ void __launch_bounds__(128) k_loss(float* __restrict__ out) {
    const int warp = threadIdx.x >> 5;
    const int lane = threadIdx.x & 31;
    const int batch = blockIdx.x / BLOCKS_PER_BATCH;
    const int row0 = (blockIdx.x % BLOCKS_PER_BATCH) * ROWS_PER_BLOCK + warp * ROWS_PER_WARP;
    const int base = batch * NB;

    float4 R[ROWS_PER_WARP];
    float  U[ROWS_PER_WARP];
#pragma unroll
    for (int j = 0; j < ROWS_PER_WARP; j++) {
        R[j] = g_xp[base + row0 + j];
        U[j] = g_u[base + row0 + j];
    }

    float tot = 0.0f;
    for (int t = 0; t < NB / 32; t++) {
        int k = base + t * 32 + lane;
        float4 C = g_yp[k];
        float  vk = g_v[k];
#pragma unroll
        for (int j = 0; j < ROWS_PER_WARP; j++) {
            float dot = R[j].x * C.x + R[j].y * C.y + R[j].z * C.z;
            float Mv  = fmaxf((R[j].w + C.w) - 2.0f * dot, 0.0f);
            float tt  = (U[j] + vk) - Mv;
            tot = fmaf(Mv, ex2f(tt * INVEPS_LOG2E), tot);
        }
    }
#pragma unroll
    for (int o = 16; o; o >>= 1)
        tot += __shfl_xor_sync(0xffffffffu, tot, o);
    if (lane == 0) atomicAdd(&out[batch], tot);
}

// ---------------------------------------------------------------------------
extern "C" void kernel_launch(void* const* d_in, const int* in_sizes, int n_in,
                              void* d_out, int out_size) {
    (void)in_sizes; (void)n_in; (void)out_size;
    const float* px = (const float*)d_in[0];   // predicted [8,2048,3]
    const float* py = (const float*)d_in[1];   // expected  [8,2048,3]
    const float* a  = (const float*)d_in[2];   // [8,2048]
    const float* b  = (const float*)d_in[3];   // [8,2048]
    float* out = (float*)d_out;                // [8]

    k_init<<<(MB * NB + 255) / 256, 256>>>(px, py, a, b, out);
    for (int t = 0; t < NITERS; t++) {
        k_half<0><<<GRID_HALF, 128>>>(t);
        k_half<1><<<GRID_HALF, 128>>>(t);
    }
    k_loss<<<GRID_HALF, 128>>>(out);
}

// round 3
// speedup vs baseline: 2.4149x; 2.4149x over previous
#include <cuda_runtime.h>
#include <math.h>

// ---------------------------------------------------------------------------
// SinkhornLoss: m=8, n=2048, d=3, eps=1e-3, 50 iters, early-stop flag.
// Never materialize M. All exponent math in the pre-scaled domain:
//   chain(i,k) = c*(p_k - M_ik) + c*||x_i||^2, with c = log2e/eps,
// computed as ONE 3-FMA chain from coords pre-scaled by 2c and a per-column
// base qb = c*p_k - c*||y_k||^2. The per-row c*||x||^2 cancels in the
// max-shift, so pass2 is 3 FMA + add + ex2 + add per entry.
// ---------------------------------------------------------------------------

#define MB     8
#define NB     2048
#define EPSF   1e-3f
#define THRESH 1e-3f
#define NITERS 50
#define CSC    1442.6950408889634f      // log2(e)/eps
#define INVC   6.931471805599453e-4f    // 1/CSC = eps*ln2

#define ROWS 8                           // rows per block
#define WPB  4                           // warps per block (column split)
#define CPW  (NB / WPB)                  // 512 columns per warp
#define TPW  (CPW / 32)                  // 16 tile iters per warp
#define RGPB (NB / ROWS)                 // 256 row-groups per batch
#define GRID_HALF (MB * RGPB)            // 2048 blocks

// Scratch (allocation-free rule: __device__ globals)
__device__ float4   g_x[MB * NB];   // {x0, x1, x2, c*||x||^2}
__device__ float4   g_y[MB * NB];   // {y0, y1, y2, c*||y||^2}
__device__ float    g_u[MB * NB];
__device__ float    g_v[MB * NB];
__device__ float    g_la[MB * NB];
__device__ float    g_lb[MB * NB];
__device__ unsigned g_err[NITERS];  // per-iteration max(err_u, err_v), float bits

__device__ __forceinline__ float ex2f(float x) {
    float r;
    asm("ex2.approx.ftz.f32 %0, %1;" : "=f"(r) : "f"(x));
    return r;
}

// ---------------------------------------------------------------------------
__global__ void k_init(const float* __restrict__ px, const float* __restrict__ py,
                       const float* __restrict__ a, const float* __restrict__ b,
                       float* __restrict__ out) {
    int i = blockIdx.x * blockDim.x + threadIdx.x;
    if (i < MB * NB) {
        float x0 = px[3 * i], x1 = px[3 * i + 1], x2 = px[3 * i + 2];
        g_x[i] = make_float4(x0, x1, x2, CSC * (x0 * x0 + x1 * x1 + x2 * x2));
        float y0 = py[3 * i], y1 = py[3 * i + 1], y2 = py[3 * i + 2];
        g_y[i] = make_float4(y0, y1, y2, CSC * (y0 * y0 + y1 * y1 + y2 * y2));
        g_u[i] = 0.0f;
        g_v[i] = 0.0f;
        g_la[i] = logf(a[i]);
        g_lb[i] = logf(b[i]);
    }
    if (i < NITERS) g_err[i] = 0u;
    if (i < MB)     out[i] = 0.0f;
}

// ---------------------------------------------------------------------------
// One half Sinkhorn update. SIDE=0 updates u (rows=x), SIDE=1 updates v (rows=y).
template <int SIDE>
__global__ void __launch_bounds__(128, 9) k_half(int iter) {
    __shared__ float s_mx[WPB][ROWS];
    __shared__ float s_sm[WPB][ROWS];
    __shared__ int s_done;
    if (threadIdx.x == 0) {
        int d = 0;
        for (int s = 0; s < iter; s++)
            d |= (__uint_as_float(g_err[s]) < THRESH) ? 1 : 0;
        s_done = d;
    }
    __syncthreads();
    if (s_done) return;   // frozen once converged (reference semantics)

    const int warp  = threadIdx.x >> 5;
    const int lane  = threadIdx.x & 31;
    const int batch = blockIdx.x / RGPB;
    const int row0  = (blockIdx.x % RGPB) * ROWS;
    const int base  = batch * NB;

    const float4* __restrict__ rp  = SIDE ? g_y : g_x;   // row-side coords
    const float4* __restrict__ cp  = SIDE ? g_x : g_y;   // col-side coords
    const float*  __restrict__ pot = SIDE ? g_u : g_v;   // col-side potential
    float*                     upd = SIDE ? g_v : g_u;   // side being updated
    const float*  __restrict__ rl  = SIDE ? g_lb : g_la; // row-side log marginal

    float cx[ROWS], cy[ROWS], cz[ROWS], mxs[ROWS];
#pragma unroll
    for (int j = 0; j < ROWS; j++) {
        float4 R = rp[base + row0 + j];
        cx[j] = R.x * (2.0f * CSC);
        cy[j] = R.y * (2.0f * CSC);
        cz[j] = R.z * (2.0f * CSC);
        mxs[j] = -3.4e38f;
    }
    const int kbeg = base + warp * CPW + lane;

    // ---- Pass 1: row max of chain = c*(p - M) + c*x2 (shift const per row)
#pragma unroll 2
    for (int t = 0; t < TPW; t++) {
        int k = kbeg + t * 32;
        float4 C = cp[k];
        float qb = fmaf(pot[k], CSC, -C.w);          // c*p - c*y2
#pragma unroll
        for (int j = 0; j < ROWS; j++) {
            float s = fmaf(cx[j], C.x, fmaf(cy[j], C.y, fmaf(cz[j], C.z, qb)));
            mxs[j] = fmaxf(mxs[j], s);
        }
    }
#pragma unroll
    for (int j = 0; j < ROWS; j++) {
#pragma unroll
        for (int o = 16; o; o >>= 1)
            mxs[j] = fmaxf(mxs[j], __shfl_xor_sync(0xffffffffu, mxs[j], o));
    }
    if (lane == 0) {
#pragma unroll
        for (int j = 0; j < ROWS; j++) s_mx[warp][j] = mxs[j];
    }
    __syncthreads();
#pragma unroll
    for (int j = 0; j < ROWS; j++) {
        float a01 = fmaxf(s_mx[0][j], s_mx[1][j]);
        float a23 = fmaxf(s_mx[2][j], s_mx[3][j]);
        mxs[j] = fmaxf(a01, a23);
    }

    // ---- Pass 2: row sum of ex2(chain - mxs)  (== exp((s - mx)/eps))
    float sm[ROWS];
#pragma unroll
    for (int j = 0; j < ROWS; j++) sm[j] = 0.0f;

#pragma unroll 2
    for (int t = 0; t < TPW; t++) {
        int k = kbeg + t * 32;
        float4 C = cp[k];
        float qb = fmaf(pot[k], CSC, -C.w);
#pragma unroll
        for (int j = 0; j < ROWS; j++) {
            float arg = fmaf(cx[j], C.x, fmaf(cy[j], C.y, fmaf(cz[j], C.z, qb - mxs[j])));
            sm[j] += ex2f(arg);
        }
    }
#pragma unroll
    for (int j = 0; j < ROWS; j++) {
#pragma unroll
        for (int o = 16; o; o >>= 1)
            sm[j] += __shfl_xor_sync(0xffffffffu, sm[j], o);
    }
    if (lane == 0) {
#pragma unroll
        for (int j = 0; j < ROWS; j++) s_sm[warp][j] = sm[j];
    }
    __syncthreads();

    // ---- Finalize: warp 0, lanes 0..7 each own one row
    if (warp == 0 && lane < ROWS) {
        int r = base + row0 + lane;
        float smv = (s_sm[0][lane] + s_sm[1][lane]) + (s_sm[2][lane] + s_sm[3][lane]);
        float m01 = fmaxf(s_mx[0][lane], s_mx[1][lane]);
        float m23 = fmaxf(s_mx[2][lane], s_mx[3][lane]);
        float mxc = fmaxf(m01, m23);
        float x2c = rp[r].w;                         // c*||x||^2
        float mx_row = (mxc - x2c) * INVC;           // true max of (p - M)
        float nv = EPSF * rl[r] - mx_row - EPSF * __logf(smv);
        float ov = upd[r];
        upd[r] = nv;
        float e = fabsf(nv - ov);
#pragma unroll
        for (int o = 4; o; o >>= 1)
            e = fmaxf(e, __shfl_xor_sync(0x000000ffu, e, o));
        if (lane == 0)
            atomicMax(&g_err[iter], __float_as_uint(e));  // e>=0: uint order==float order
    }
}

// ---------------------------------------------------------------------------
// loss[b] = sum_{i,k} M * exp((u_i + v_k - M)/eps)
__global__ void __launch_bounds__(128, 9) k_loss(float* __restrict__ out) {
    const int warp  = threadIdx.x >> 5;
    const int lane  = threadIdx.x & 31;
    const int batch = blockIdx.x / RGPB;
    const int row0  = (blockIdx.x % RGPB) * ROWS;
    const int base  = batch * NB;

    float cx[ROWS], cy[ROWS], cz[ROWS], aj[ROWS], U[ROWS];
#pragma unroll
    for (int j = 0; j < ROWS; j++) {
        float4 R = g_x[base + row0 + j];
        cx[j] = R.x * (2.0f * CSC);
        cy[j] = R.y * (2.0f * CSC);
        cz[j] = R.z * (2.0f * CSC);
        U[j]  = g_u[base + row0 + j];
        aj[j] = fmaf(U[j], CSC, -R.w);               // c*u - c*x2
    }
    const int kbeg = base + warp * CPW + lane;

    float tot = 0.0f;
#pragma unroll 2
    for (int t = 0; t < TPW; t++) {
        int k = kbeg + t * 32;
        float4 C = g_y[k];
        float vk = g_v[k];
        float qb = fmaf(vk, CSC, -C.w);              // c*v - c*y2
#pragma unroll
        for (int j = 0; j < ROWS; j++) {
            // carg = c*(u + v - M)
            float carg = fmaf(cx[j], C.x, fmaf(cy[j], C.y, fmaf(cz[j], C.z, qb + aj[j])));
            float e  = ex2f(carg);
            float uv = U[j] + vk;
            float Mv = fmaf(carg, -INVC, uv);        // = M (unclamped)
            tot = fmaf(Mv, e, tot);
        }
    }
#pragma unroll
    for (int o = 16; o; o >>= 1)
        tot += __shfl_xor_sync(0xffffffffu, tot, o);
    if (lane == 0) atomicAdd(&out[batch], tot);
}

// ---------------------------------------------------------------------------
extern "C" void kernel_launch(void* const* d_in, const int* in_sizes, int n_in,
                              void* d_out, int out_size) {
    (void)in_sizes; (void)n_in; (void)out_size;
    const float* px = (const float*)d_in[0];   // predicted [8,2048,3]
    const float* py = (const float*)d_in[1];   // expected  [8,2048,3]
    const float* a  = (const float*)d_in[2];   // [8,2048]
    const float* b  = (const float*)d_in[3];   // [8,2048]
    float* out = (float*)d_out;                // [8]

    k_init<<<(MB * NB + 255) / 256, 256>>>(px, py, a, b, out);
    for (int t = 0; t < NITERS; t++) {
        k_half<0><<<GRID_HALF, 128>>>(t);
        k_half<1><<<GRID_HALF, 128>>>(t);
    }
    k_loss<<<GRID_HALF, 128>>>(out);
}

// round 4
// speedup vs baseline: 3.0628x; 1.2683x over previous
#include <cuda_runtime.h>
#include <math.h>

// ---------------------------------------------------------------------------
// SinkhornLoss: m=8, n=2048, d=3, eps=1e-3, 50 iters, early-stop flag.
// M never materialized. Exponent math in pre-scaled domain:
//   chain(i,k) = c*(p_k - M_ik) + c*||x_i||^2, c = log2e/eps,
// as one 3-FMA chain from coords pre-scaled by 2c and per-column base
// qb = c*p_k - c*||y_k||^2. Rows processed in f32x2 PAIRS via fma.rn.f32x2
// (FFMA2) to halve fma-pipe issue slots; row max via scalar FMNMX (alu pipe).
// ---------------------------------------------------------------------------

#define MB     8
#define NB     2048
#define EPSF   1e-3f
#define THRESH 1e-3f
#define NITERS 50
#define CSC    1442.6950408889634f      // log2(e)/eps
#define INVC   6.931471805599453e-4f    // 1/CSC = eps*ln2

#define ROWS 8                           // rows per block (4 f32x2 pairs)
#define PAIRS (ROWS / 2)
#define WPB  4                           // warps per block (column split)
#define CPW  (NB / WPB)                  // 512 columns per warp
#define TPW  (CPW / 32)                  // 16 tile iters per warp
#define RGPB (NB / ROWS)                 // 256 row-groups per batch
#define GRID_HALF (MB * RGPB)            // 2048 blocks

typedef unsigned long long u64;

// Scratch (allocation-free rule: __device__ globals)
__device__ float4   g_x[MB * NB];   // {x0, x1, x2, c*||x||^2}
__device__ float4   g_y[MB * NB];   // {y0, y1, y2, c*||y||^2}
__device__ float    g_u[MB * NB];
__device__ float    g_v[MB * NB];
__device__ float    g_la[MB * NB];
__device__ float    g_lb[MB * NB];
__device__ unsigned g_err[NITERS];  // per-iteration max(err_u, err_v), float bits

__device__ __forceinline__ float ex2f(float x) {
    float r; asm("ex2.approx.ftz.f32 %0, %1;" : "=f"(r) : "f"(x)); return r;
}
__device__ __forceinline__ u64 pack2(float lo, float hi) {
    u64 r; asm("mov.b64 %0, {%1, %2};" : "=l"(r) : "f"(lo), "f"(hi)); return r;
}
__device__ __forceinline__ float lo2(u64 p) {
    float l, h; asm("mov.b64 {%0, %1}, %2;" : "=f"(l), "=f"(h) : "l"(p)); return l;
}
__device__ __forceinline__ float hi2(u64 p) {
    float l, h; asm("mov.b64 {%0, %1}, %2;" : "=f"(l), "=f"(h) : "l"(p)); return h;
}
__device__ __forceinline__ u64 fma2(u64 a, u64 b, u64 c) {
    u64 d; asm("fma.rn.f32x2 %0, %1, %2, %3;" : "=l"(d) : "l"(a), "l"(b), "l"(c)); return d;
}
__device__ __forceinline__ u64 add2(u64 a, u64 b) {
    u64 d; asm("add.rn.f32x2 %0, %1, %2;" : "=l"(d) : "l"(a), "l"(b)); return d;
}

// ---------------------------------------------------------------------------
__global__ void k_init(const float* __restrict__ px, const float* __restrict__ py,
                       const float* __restrict__ a, const float* __restrict__ b,
                       float* __restrict__ out) {
    int i = blockIdx.x * blockDim.x + threadIdx.x;
    if (i < MB * NB) {
        float x0 = px[3 * i], x1 = px[3 * i + 1], x2 = px[3 * i + 2];
        g_x[i] = make_float4(x0, x1, x2, CSC * (x0 * x0 + x1 * x1 + x2 * x2));
        float y0 = py[3 * i], y1 = py[3 * i + 1], y2 = py[3 * i + 2];
        g_y[i] = make_float4(y0, y1, y2, CSC * (y0 * y0 + y1 * y1 + y2 * y2));
        g_u[i] = 0.0f;
        g_v[i] = 0.0f;
        g_la[i] = logf(a[i]);
        g_lb[i] = logf(b[i]);
    }
    if (i < NITERS) g_err[i] = 0u;
    if (i < MB)     out[i] = 0.0f;
}

// ---------------------------------------------------------------------------
// One half Sinkhorn update. SIDE=0 updates u (rows=x), SIDE=1 updates v (rows=y).
template <int SIDE>
__global__ void __launch_bounds__(128, 8) k_half(int iter) {
    __shared__ float s_mx[WPB][ROWS];
    __shared__ float s_sm[WPB][ROWS];
    __shared__ int s_done;
    if (threadIdx.x == 0) {
        int d = 0;
        for (int s = 0; s < iter; s++)
            d |= (__uint_as_float(g_err[s]) < THRESH) ? 1 : 0;
        s_done = d;
    }
    __syncthreads();
    if (s_done) return;   // frozen once converged (reference semantics)

    const int warp  = threadIdx.x >> 5;
    const int lane  = threadIdx.x & 31;
    const int batch = blockIdx.x / RGPB;
    const int row0  = (blockIdx.x % RGPB) * ROWS;
    const int base  = batch * NB;

    const float4* __restrict__ rp  = SIDE ? g_y : g_x;   // row-side coords
    const float4* __restrict__ cp  = SIDE ? g_x : g_y;   // col-side coords
    const float*  __restrict__ pot = SIDE ? g_u : g_v;   // col-side potential
    float*                     upd = SIDE ? g_v : g_u;   // side being updated
    const float*  __restrict__ rl  = SIDE ? g_lb : g_la; // row-side log marginal

    // Row-pair packed coordinates, pre-scaled by 2c
    u64 cx2[PAIRS], cy2[PAIRS], cz2[PAIRS];
    float mxs[ROWS];
#pragma unroll
    for (int p = 0; p < PAIRS; p++) {
        float4 R0 = rp[base + row0 + 2 * p];
        float4 R1 = rp[base + row0 + 2 * p + 1];
        cx2[p] = pack2(R0.x * (2.0f * CSC), R1.x * (2.0f * CSC));
        cy2[p] = pack2(R0.y * (2.0f * CSC), R1.y * (2.0f * CSC));
        cz2[p] = pack2(R0.z * (2.0f * CSC), R1.z * (2.0f * CSC));
    }
#pragma unroll
    for (int j = 0; j < ROWS; j++) mxs[j] = -3.4e38f;
    const int kbeg = base + warp * CPW + lane;

    // ---- Pass 1: row max of chain = c*(p - M) + c*x2 (shift const per row)
#pragma unroll 2
    for (int t = 0; t < TPW; t++) {
        int k = kbeg + t * 32;
        float4 C = cp[k];
        float qb = fmaf(pot[k], CSC, -C.w);          // c*p - c*y2
        u64 Cx = pack2(C.x, C.x), Cy = pack2(C.y, C.y), Cz = pack2(C.z, C.z);
        u64 qb2 = pack2(qb, qb);
#pragma unroll
        for (int p = 0; p < PAIRS; p++) {
            u64 s2 = fma2(cx2[p], Cx, fma2(cy2[p], Cy, fma2(cz2[p], Cz, qb2)));
            mxs[2 * p]     = fmaxf(mxs[2 * p],     lo2(s2));
            mxs[2 * p + 1] = fmaxf(mxs[2 * p + 1], hi2(s2));
        }
    }
#pragma unroll
    for (int j = 0; j < ROWS; j++) {
#pragma unroll
        for (int o = 16; o; o >>= 1)
            mxs[j] = fmaxf(mxs[j], __shfl_xor_sync(0xffffffffu, mxs[j], o));
    }
    if (lane == 0) {
#pragma unroll
        for (int j = 0; j < ROWS; j++) s_mx[warp][j] = mxs[j];
    }
    __syncthreads();
#pragma unroll
    for (int j = 0; j < ROWS; j++) {
        float a01 = fmaxf(s_mx[0][j], s_mx[1][j]);
        float a23 = fmaxf(s_mx[2][j], s_mx[3][j]);
        mxs[j] = fmaxf(a01, a23);
    }
    u64 nmx2[PAIRS];
#pragma unroll
    for (int p = 0; p < PAIRS; p++)
        nmx2[p] = pack2(-mxs[2 * p], -mxs[2 * p + 1]);

    // ---- Pass 2: row sum of ex2(chain - mxs)  (same chain bits => arg <= 0)
    float sm[ROWS];
#pragma unroll
    for (int j = 0; j < ROWS; j++) sm[j] = 0.0f;

#pragma unroll 2
    for (int t = 0; t < TPW; t++) {
        int k = kbeg + t * 32;
        float4 C = cp[k];
        float qb = fmaf(pot[k], CSC, -C.w);
        u64 Cx = pack2(C.x, C.x), Cy = pack2(C.y, C.y), Cz = pack2(C.z, C.z);
        u64 qb2 = pack2(qb, qb);
#pragma unroll
        for (int p = 0; p < PAIRS; p++) {
            u64 s2 = fma2(cx2[p], Cx, fma2(cy2[p], Cy, fma2(cz2[p], Cz, qb2)));
            u64 a2 = add2(s2, nmx2[p]);
            sm[2 * p]     += ex2f(lo2(a2));
            sm[2 * p + 1] += ex2f(hi2(a2));
        }
    }
#pragma unroll
    for (int j = 0; j < ROWS; j++) {
#pragma unroll
        for (int o = 16; o; o >>= 1)
            sm[j] += __shfl_xor_sync(0xffffffffu, sm[j], o);
    }
    if (lane == 0) {
#pragma unroll
        for (int j = 0; j < ROWS; j++) s_sm[warp][j] = sm[j];
    }
    __syncthreads();

    // ---- Finalize: warp 0, lanes 0..7 each own one row
    if (warp == 0 && lane < ROWS) {
        int r = base + row0 + lane;
        float smv = (s_sm[0][lane] + s_sm[1][lane]) + (s_sm[2][lane] + s_sm[3][lane]);
        float m01 = fmaxf(s_mx[0][lane], s_mx[1][lane]);
        float m23 = fmaxf(s_mx[2][lane], s_mx[3][lane]);
        float mxc = fmaxf(m01, m23);
        float x2c = rp[r].w;                         // c*||x||^2
        float mx_row = (mxc - x2c) * INVC;           // true max of (p - M)
        float nv = EPSF * rl[r] - mx_row - EPSF * __logf(smv);
        float ov = upd[r];
        upd[r] = nv;
        float e = fabsf(nv - ov);
#pragma unroll
        for (int o = 4; o; o >>= 1)
            e = fmaxf(e, __shfl_xor_sync(0x000000ffu, e, o));
        if (lane == 0)
            atomicMax(&g_err[iter], __float_as_uint(e));  // e>=0: uint order==float order
    }
}

// ---------------------------------------------------------------------------
// loss[b] = sum_{i,k} M * exp((u_i + v_k - M)/eps)
__global__ void __launch_bounds__(128, 8) k_loss(float* __restrict__ out) {
    const int warp  = threadIdx.x >> 5;
    const int lane  = threadIdx.x & 31;
    const int batch = blockIdx.x / RGPB;
    const int row0  = (blockIdx.x % RGPB) * ROWS;
    const int base  = batch * NB;

    float cx[ROWS], cy[ROWS], cz[ROWS], aj[ROWS], U[ROWS];
#pragma unroll
    for (int j = 0; j < ROWS; j++) {
        float4 R = g_x[base + row0 + j];
        cx[j] = R.x * (2.0f * CSC);
        cy[j] = R.y * (2.0f * CSC);
        cz[j] = R.z * (2.0f * CSC);
        U[j]  = g_u[base + row0 + j];
        aj[j] = fmaf(U[j], CSC, -R.w);               // c*u - c*x2
    }
    const int kbeg = base + warp * CPW + lane;

    float tot = 0.0f;
#pragma unroll 2
    for (int t = 0; t < TPW; t++) {
        int k = kbeg + t * 32;
        float4 C = g_y[k];
        float vk = g_v[k];
        float qb = fmaf(vk, CSC, -C.w);              // c*v - c*y2
#pragma unroll
        for (int j = 0; j < ROWS; j++) {
            // carg = c*(u + v - M)
            float carg = fmaf(cx[j], C.x, fmaf(cy[j], C.y, fmaf(cz[j], C.z, qb + aj[j])));
            float e  = ex2f(carg);
            float uv = U[j] + vk;
            float Mv = fmaf(carg, -INVC, uv);        // = M (unclamped)
            tot = fmaf(Mv, e, tot);
        }
    }
#pragma unroll
    for (int o = 16; o; o >>= 1)
        tot += __shfl_xor_sync(0xffffffffu, tot, o);
    if (lane == 0) atomicAdd(&out[batch], tot);
}

// ---------------------------------------------------------------------------
extern "C" void kernel_launch(void* const* d_in, const int* in_sizes, int n_in,
                              void* d_out, int out_size) {
    (void)in_sizes; (void)n_in; (void)out_size;
    const float* px = (const float*)d_in[0];   // predicted [8,2048,3]
    const float* py = (const float*)d_in[1];   // expected  [8,2048,3]
    const float* a  = (const float*)d_in[2];   // [8,2048]
    const float* b  = (const float*)d_in[3];   // [8,2048]
    float* out = (float*)d_out;                // [8]

    k_init<<<(MB * NB + 255) / 256, 256>>>(px, py, a, b, out);
    for (int t = 0; t < NITERS; t++) {
        k_half<0><<<GRID_HALF, 128>>>(t);
        k_half<1><<<GRID_HALF, 128>>>(t);
    }
    k_loss<<<GRID_HALF, 128>>>(out);
}

// round 5
// speedup vs baseline: 3.3127x; 1.0816x over previous
#include <cuda_runtime.h>
#include <math.h>

// ---------------------------------------------------------------------------
// SinkhornLoss: m=8, n=2048, d=3, eps=1e-3, 50 iters, early-stop flag.
// chain(i,k) = 2c*x_i.y_k + qb_k, qb_k = c*pot_k - c*||y_k||^2 (stored in the
// column float4's .w, refreshed by the previous half's finalize). Rows in
// f32x2 pairs (FFMA2). 64-thread blocks, 16/SM -> single co-resident wave.
// ---------------------------------------------------------------------------

#define MB     8
#define NB     2048
#define EPSF   1e-3f
#define THRESH 1e-3f
#define NITERS 50
#define CSC    1442.6950408889634f      // log2(e)/eps
#define INVC   6.931471805599453e-4f    // 1/CSC = eps*ln2

#define ROWS   8                         // rows per block (4 f32x2 pairs)
#define PAIRS  (ROWS / 2)
#define WPB    2                         // warps per block (column split)
#define THREADS (WPB * 32)
#define CPW    (NB / WPB)                // 1024 columns per warp
#define TPW    (CPW / 32)                // 32 tile iters per warp
#define RGPB   (NB / ROWS)               // 256 row-groups per batch
#define GRID_HALF (MB * RGPB)            // 2048 blocks

typedef unsigned long long u64;

// Scratch (allocation-free rule: __device__ globals)
__device__ float4   g_cx[MB * NB];  // {x0,x1,x2, c*u - c*||x||^2}
__device__ float4   g_cy[MB * NB];  // {y0,y1,y2, c*v - c*||y||^2}
__device__ float    g_n2x[MB * NB]; // c*||x||^2 (exact, no drift)
__device__ float    g_n2y[MB * NB]; // c*||y||^2
__device__ float    g_u[MB * NB];
__device__ float    g_v[MB * NB];
__device__ float    g_la[MB * NB];
__device__ float    g_lb[MB * NB];
__device__ unsigned g_err[NITERS];  // per-iter max(err_u, err_v), float bits
__device__ int      g_done;         // sticky convergence flag

__device__ __forceinline__ float ex2f(float x) {
    float r; asm("ex2.approx.ftz.f32 %0, %1;" : "=f"(r) : "f"(x)); return r;
}
__device__ __forceinline__ u64 pack2(float lo, float hi) {
    u64 r; asm("mov.b64 %0, {%1, %2};" : "=l"(r) : "f"(lo), "f"(hi)); return r;
}
__device__ __forceinline__ float lo2(u64 p) {
    float l, h; asm("mov.b64 {%0, %1}, %2;" : "=f"(l), "=f"(h) : "l"(p)); return l;
}
__device__ __forceinline__ float hi2(u64 p) {
    float l, h; asm("mov.b64 {%0, %1}, %2;" : "=f"(l), "=f"(h) : "l"(p)); return h;
}
__device__ __forceinline__ u64 fma2(u64 a, u64 b, u64 c) {
    u64 d; asm("fma.rn.f32x2 %0, %1, %2, %3;" : "=l"(d) : "l"(a), "l"(b), "l"(c)); return d;
}
__device__ __forceinline__ u64 add2(u64 a, u64 b) {
    u64 d; asm("add.rn.f32x2 %0, %1, %2;" : "=l"(d) : "l"(a), "l"(b)); return d;
}

// ---------------------------------------------------------------------------
__global__ void k_init(const float* __restrict__ px, const float* __restrict__ py,
                       const float* __restrict__ a, const float* __restrict__ b,
                       float* __restrict__ out) {
    int i = blockIdx.x * blockDim.x + threadIdx.x;
    if (i < MB * NB) {
        float x0 = px[3 * i], x1 = px[3 * i + 1], x2 = px[3 * i + 2];
        float n2x = CSC * (x0 * x0 + x1 * x1 + x2 * x2);
        g_cx[i] = make_float4(x0, x1, x2, -n2x);     // u = 0
        g_n2x[i] = n2x;
        float y0 = py[3 * i], y1 = py[3 * i + 1], y2 = py[3 * i + 2];
        float n2y = CSC * (y0 * y0 + y1 * y1 + y2 * y2);
        g_cy[i] = make_float4(y0, y1, y2, -n2y);     // v = 0
        g_n2y[i] = n2y;
        g_u[i] = 0.0f;
        g_v[i] = 0.0f;
        g_la[i] = logf(a[i]);
        g_lb[i] = logf(b[i]);
    }
    if (i < NITERS) g_err[i] = 0u;
    if (i == 0)     g_done = 0;
    if (i < MB)     out[i] = 0.0f;
}

// ---------------------------------------------------------------------------
// One half Sinkhorn update. SIDE=0 updates u (rows=x, cols=y+v);
//                           SIDE=1 updates v (rows=y, cols=x+u).
template <int SIDE>
__global__ void __launch_bounds__(THREADS, 16) k_half(int iter) {
    __shared__ float s_mx[WPB][ROWS];
    __shared__ float s_sm[WPB][ROWS];
    __shared__ int s_done;
    if (threadIdx.x == 0) {
        int d = g_done;
        if (!d && iter > 0 && __uint_as_float(g_err[iter - 1]) < THRESH) {
            d = 1;
            g_done = 1;          // sticky, monotone: benign race
        }
        s_done = d;
    }
    __syncthreads();
    if (s_done) return;          // frozen once converged (reference semantics)

    const int warp  = threadIdx.x >> 5;
    const int lane  = threadIdx.x & 31;
    const int batch = blockIdx.x / RGPB;
    const int row0  = (blockIdx.x % RGPB) * ROWS;
    const int base  = batch * NB;

    const float4* __restrict__ rp  = SIDE ? g_cy : g_cx;   // row-side coords
    const float4* __restrict__ cp  = SIDE ? g_cx : g_cy;   // col-side {coords, qb}
    float4*                    rw  = SIDE ? g_cy : g_cx;   // row-side (finalize .w write)
    const float*  __restrict__ n2  = SIDE ? g_n2y : g_n2x; // c*||row||^2
    float*                     upd = SIDE ? g_v : g_u;     // potential being updated
    const float*  __restrict__ rl  = SIDE ? g_lb : g_la;   // row-side log marginal

    // Row-pair packed coordinates, pre-scaled by 2c
    u64 cx2[PAIRS], cy2[PAIRS], cz2[PAIRS];
    float mxs[ROWS];
#pragma unroll
    for (int p = 0; p < PAIRS; p++) {
        float4 R0 = rp[base + row0 + 2 * p];
        float4 R1 = rp[base + row0 + 2 * p + 1];
        cx2[p] = pack2(R0.x * (2.0f * CSC), R1.x * (2.0f * CSC));
        cy2[p] = pack2(R0.y * (2.0f * CSC), R1.y * (2.0f * CSC));
        cz2[p] = pack2(R0.z * (2.0f * CSC), R1.z * (2.0f * CSC));
    }
#pragma unroll
    for (int j = 0; j < ROWS; j++) mxs[j] = -3.4e38f;
    const int kbeg = base + warp * CPW + lane;

    // ---- Pass 1: row max of chain = 2c*x.y + qb
#pragma unroll 2
    for (int t = 0; t < TPW; t++) {
        int k = kbeg + t * 32;
        float4 C = cp[k];                        // {c0,c1,c2, qb}
        u64 Cx = pack2(C.x, C.x), Cy = pack2(C.y, C.y), Cz = pack2(C.z, C.z);
        u64 Q  = pack2(C.w, C.w);
#pragma unroll
        for (int p = 0; p < PAIRS; p++) {
            u64 s2 = fma2(cx2[p], Cx, fma2(cy2[p], Cy, fma2(cz2[p], Cz, Q)));
            mxs[2 * p]     = fmaxf(mxs[2 * p],     lo2(s2));
            mxs[2 * p + 1] = fmaxf(mxs[2 * p + 1], hi2(s2));
        }
    }
#pragma unroll
    for (int j = 0; j < ROWS; j++) {
#pragma unroll
        for (int o = 16; o; o >>= 1)
            mxs[j] = fmaxf(mxs[j], __shfl_xor_sync(0xffffffffu, mxs[j], o));
    }
    if (lane == 0) {
#pragma unroll
        for (int j = 0; j < ROWS; j++) s_mx[warp][j] = mxs[j];
    }
    __syncthreads();
    u64 nmx2[PAIRS];
#pragma unroll
    for (int p = 0; p < PAIRS; p++) {
        float m0 = fmaxf(s_mx[0][2 * p],     s_mx[1][2 * p]);
        float m1 = fmaxf(s_mx[0][2 * p + 1], s_mx[1][2 * p + 1]);
        nmx2[p] = pack2(-m0, -m1);
    }

    // ---- Pass 2: row sum of ex2(chain - mx)  (same chain bits => arg <= 0)
    float sm[ROWS];
#pragma unroll
    for (int j = 0; j < ROWS; j++) sm[j] = 0.0f;

#pragma unroll 2
    for (int t = 0; t < TPW; t++) {
        int k = kbeg + t * 32;
        float4 C = cp[k];
        u64 Cx = pack2(C.x, C.x), Cy = pack2(C.y, C.y), Cz = pack2(C.z, C.z);
        u64 Q  = pack2(C.w, C.w);
#pragma unroll
        for (int p = 0; p < PAIRS; p++) {
            u64 s2 = fma2(cx2[p], Cx, fma2(cy2[p], Cy, fma2(cz2[p], Cz, Q)));
            u64 a2 = add2(s2, nmx2[p]);
            sm[2 * p]     += ex2f(lo2(a2));
            sm[2 * p + 1] += ex2f(hi2(a2));
        }
    }
#pragma unroll
    for (int j = 0; j < ROWS; j++) {
#pragma unroll
        for (int o = 16; o; o >>= 1)
            sm[j] += __shfl_xor_sync(0xffffffffu, sm[j], o);
    }
    if (lane == 0) {
#pragma unroll
        for (int j = 0; j < ROWS; j++) s_sm[warp][j] = sm[j];
    }
    __syncthreads();

    // ---- Finalize: warp 0, lanes 0..7 each own one row
    if (warp == 0 && lane < ROWS) {
        int r = base + row0 + lane;
        float smv = s_sm[0][lane] + s_sm[1][lane];
        float mxc = fmaxf(s_mx[0][lane], s_mx[1][lane]);
        float n2r = n2[r];                           // c*||row||^2 (exact)
        float mx_row = (mxc - n2r) * INVC;           // true max of (pot - M)
        float nv = EPSF * rl[r] - mx_row - EPSF * __logf(smv);
        float ov = upd[r];
        upd[r] = nv;
        // refresh this row's column-side qb: c*pot_new - c*||row||^2
        ((float*)(rw + r))[3] = fmaf(CSC, nv, -n2r);
        float e = fabsf(nv - ov);
#pragma unroll
        for (int o = 4; o; o >>= 1)
            e = fmaxf(e, __shfl_xor_sync(0x000000ffu, e, o));
        if (lane == 0)
            atomicMax(&g_err[iter], __float_as_uint(e));  // e>=0: uint order==float order
    }
}

// ---------------------------------------------------------------------------
// loss[b] = sum_{i,k} M * exp((u_i + v_k - M)/eps)
__global__ void __launch_bounds__(THREADS, 16) k_loss(float* __restrict__ out) {
    const int warp  = threadIdx.x >> 5;
    const int lane  = threadIdx.x & 31;
    const int batch = blockIdx.x / RGPB;
    const int row0  = (blockIdx.x % RGPB) * ROWS;
    const int base  = batch * NB;

    float cx[ROWS], cy[ROWS], cz[ROWS], aj[ROWS], U[ROWS];
#pragma unroll
    for (int j = 0; j < ROWS; j++) {
        float4 R = g_cx[base + row0 + j];            // {x, c*u - c*x2}
        cx[j] = R.x * (2.0f * CSC);
        cy[j] = R.y * (2.0f * CSC);
        cz[j] = R.z * (2.0f * CSC);
        aj[j] = R.w;
        U[j]  = g_u[base + row0 + j];
    }
    const int kbeg = base + warp * CPW + lane;

    float tot = 0.0f;
#pragma unroll 2
    for (int t = 0; t < TPW; t++) {
        int k = kbeg + t * 32;
        float4 C = g_cy[k];                          // {y, c*v - c*y2}
        float vk = g_v[k];
#pragma unroll
        for (int j = 0; j < ROWS; j++) {
            // carg = c*(u + v - M)
            float carg = fmaf(cx[j], C.x, fmaf(cy[j], C.y, fmaf(cz[j], C.z, C.w + aj[j])));
            float e  = ex2f(carg);
            float uv = U[j] + vk;
            float Mv = fmaf(carg, -INVC, uv);        // = M (unclamped)
            tot = fmaf(Mv, e, tot);
        }
    }
#pragma unroll
    for (int o = 16; o; o >>= 1)
        tot += __shfl_xor_sync(0xffffffffu, tot, o);
    if (lane == 0) atomicAdd(&out[batch], tot);
}

// ---------------------------------------------------------------------------
extern "C" void kernel_launch(void* const* d_in, const int* in_sizes, int n_in,
                              void* d_out, int out_size) {
    (void)in_sizes; (void)n_in; (void)out_size;
    const float* px = (const float*)d_in[0];   // predicted [8,2048,3]
    const float* py = (const float*)d_in[1];   // expected  [8,2048,3]
    const float* a  = (const float*)d_in[2];   // [8,2048]
    const float* b  = (const float*)d_in[3];   // [8,2048]
    float* out = (float*)d_out;                // [8]

    k_init<<<(MB * NB + 255) / 256, 256>>>(px, py, a, b, out);
    for (int t = 0; t < NITERS; t++) {
        k_half<0><<<GRID_HALF, THREADS>>>(t);
        k_half<1><<<GRID_HALF, THREADS>>>(t);
    }
    k_loss<<<GRID_HALF, THREADS>>>(out);
}